// round 2
// baseline (speedup 1.0000x reference)
#include <cuda_runtime.h>
#include <cstdint>

#define NG   2048
#define MAXN 500000
#define BN_EPS 1e-5f

// ---------------- scratch (device globals; no allocation allowed) ----------------
__device__ __align__(16) float g_h[(size_t)MAXN * 128];   // h, then y0 in-place (256MB)
__device__ __align__(16) float g_lam1[NG * 128];
__device__ __align__(16) float g_lam2[NG * 128];
__device__ __align__(16) float g_psum[NG * 128];
__device__ __align__(16) float g_psq[NG * 128];
__device__ __align__(16) float g_scale[128];
__device__ __align__(16) float g_shift[128];
__device__ int g_seg[NG + 1];

// ---------------- packed f32x2 helpers (FFMA2 path, sm_100+) ----------------
__device__ __forceinline__ unsigned long long pk2(float a, float b) {
    unsigned long long r;
    asm("mov.b64 %0, {%1, %2};" : "=l"(r) : "f"(a), "f"(b));
    return r;
}
__device__ __forceinline__ unsigned long long fma2(unsigned long long a,
                                                   unsigned long long b,
                                                   unsigned long long c) {
    unsigned long long d;
    asm("fma.rn.f32x2 %0, %1, %2, %3;" : "=l"(d) : "l"(a), "l"(b), "l"(c));
    return d;
}
__device__ __forceinline__ float2 upk2(unsigned long long v) {
    float2 f;
    asm("mov.b64 {%0, %1}, %2;" : "=f"(f.x), "=f"(f.y) : "l"(v));
    return f;
}

// ---------------- K0: segment bounds via binary search (batch sorted) ----------------
__global__ void k_bounds(const int* __restrict__ batch, int N) {
    int g = blockIdx.x * blockDim.x + threadIdx.x;
    if (g > NG) return;
    int lo = 0, hi = N;
    while (lo < hi) {
        int mid = (lo + hi) >> 1;
        if (batch[mid] < g) lo = mid + 1; else hi = mid;
    }
    g_seg[g] = lo;
}

// ---------------- K1: per-graph col-sums of x0 (144 cols) + lam1 = xm @ l1w^T ----------------
// blockDim = 288: two row-phases x 144 cols. Deterministic fixed-order sums.
__global__ void k_lam1(const float* __restrict__ x, const float* __restrict__ pers0,
                       const float* __restrict__ l1w, int N) {
    __shared__ float s_sum[2][144];
    __shared__ float s_xm[144];
    int g  = blockIdx.x;
    int lo = g_seg[g], hi = g_seg[g + 1];
    int t  = threadIdx.x;
    int phase = t / 144, col = t - phase * 144;

    float acc = 0.f;
    if (col < 128) {
        const float* p = x + col;
        for (int r = lo + phase; r < hi; r += 2) acc += p[(size_t)r * 128];
    } else {
        int j = col - 128;
        int pp = j >> 1, c = j & 1;
        const float* p = pers0 + (size_t)pp * 2 * N + c;
        for (int r = lo + phase; r < hi; r += 2) acc += p[2 * (size_t)r];
    }
    s_sum[phase][col] = acc;
    __syncthreads();
    if (t < 144) {
        float cnt = (float)max(hi - lo, 1);
        s_xm[t] = (s_sum[0][t] + s_sum[1][t]) / cnt;
    }
    __syncthreads();
    if (t < 128) {
        const float* w = l1w + t * 144;
        float a = 0.f;
#pragma unroll 8
        for (int k = 0; k < 144; ++k) a += s_xm[k] * w[k];
        g_lam1[g * 128 + t] = a;
    }
}

// ---------------- K2: h = relu(x0 @ g1w^T + g1b - lam1[g]) + h col-sums + lam2 ----------------
// One block per graph, 512 threads, 128-row tiles.
// smem: ws[k][j] (144 x 132 pad), xs[k][r] (144 x 132 pad) -> rows paired for f32x2.
__global__ __launch_bounds__(512, 1) void k_gemm1(
    const float* __restrict__ x, const float* __restrict__ pers0,
    const float* __restrict__ g1w, const float* __restrict__ g1b,
    const float* __restrict__ l2w, int N) {
    extern __shared__ float sm[];
    float* ws = sm;                 // [144][132]
    float* xs = sm + 144 * 132;     // [144][132] (only 128 row slots used)
    __shared__ __align__(16) float s_red[16][128];
    __shared__ float s_hm[128];

    int g   = blockIdx.x;
    int lo  = g_seg[g], hi = g_seg[g + 1];
    int tid = threadIdx.x;
    int tc  = tid & 31, tr = tid >> 5;   // cols 4*tc..4*tc+3, rows tr*8..tr*8+7

    // stage weights transposed: ws[k*132 + j] = g1w[j*144 + k]
    const float4* w4 = (const float4*)g1w;
    for (int idx = tid; idx < 128 * 36; idx += 512) {
        int j = idx / 36, k4 = idx - j * 36;
        float4 v = w4[idx];
        int k = 4 * k4;
        ws[(k + 0) * 132 + j] = v.x;
        ws[(k + 1) * 132 + j] = v.y;
        ws[(k + 2) * 132 + j] = v.z;
        ws[(k + 3) * 132 + j] = v.w;
    }

    float bias[4];
#pragma unroll
    for (int c = 0; c < 4; ++c)
        bias[c] = g1b[4 * tc + c] - g_lam1[g * 128 + 4 * tc + c];

    float hs[4] = {0.f, 0.f, 0.f, 0.f};

    for (int r0 = lo; r0 < hi; r0 += 128) {
        int rem = min(128, hi - r0);
        __syncthreads();  // previous tile's consumers done (also covers ws staging)

        // stage x part transposed: xs[k*132 + r] = x[(r0+r)*128 + k]
        const float4* x4p = (const float4*)x;
        for (int idx = tid; idx < 128 * 32; idx += 512) {
            int r = idx >> 5, k4 = idx & 31;
            float4 v = make_float4(0.f, 0.f, 0.f, 0.f);
            if (r < rem) v = x4p[(size_t)(r0 + r) * 32 + k4];
            int k = 4 * k4;
            xs[(k + 0) * 132 + r] = v.x;
            xs[(k + 1) * 132 + r] = v.y;
            xs[(k + 2) * 132 + r] = v.z;
            xs[(k + 3) * 132 + r] = v.w;
        }
        // stage pers0 part: x0[n][128 + 2p + c] = pers0[p][n][c]
        const float2* p2 = (const float2*)pers0;
        for (int idx = tid; idx < 128 * 8; idx += 512) {
            int r = idx >> 3, pp = idx & 7;
            float2 v = make_float2(0.f, 0.f);
            if (r < rem) v = p2[(size_t)pp * N + (r0 + r)];
            xs[(128 + 2 * pp) * 132 + r] = v.x;
            xs[(129 + 2 * pp) * 132 + r] = v.y;
        }
        __syncthreads();

        unsigned long long acc[4][4];
#pragma unroll
        for (int p = 0; p < 4; ++p)
#pragma unroll
            for (int c = 0; c < 4; ++c) acc[p][c] = 0ull;

#pragma unroll 4
        for (int k = 0; k < 144; ++k) {
            const float4* xr = (const float4*)(xs + k * 132);
            float4 xa = xr[2 * tr];
            float4 xb = xr[2 * tr + 1];
            float4 wv = ((const float4*)(ws + k * 132))[tc];
            unsigned long long xp[4] = {pk2(xa.x, xa.y), pk2(xa.z, xa.w),
                                        pk2(xb.x, xb.y), pk2(xb.z, xb.w)};
            unsigned long long wp[4] = {pk2(wv.x, wv.x), pk2(wv.y, wv.y),
                                        pk2(wv.z, wv.z), pk2(wv.w, wv.w)};
#pragma unroll
            for (int p = 0; p < 4; ++p)
#pragma unroll
                for (int c = 0; c < 4; ++c)
                    acc[p][c] = fma2(xp[p], wp[c], acc[p][c]);
        }

        // epilogue: relu, store h, accumulate col sums (valid rows only)
#pragma unroll
        for (int p = 0; p < 4; ++p) {
            float2 v0 = upk2(acc[p][0]);
            float2 v1 = upk2(acc[p][1]);
            float2 v2 = upk2(acc[p][2]);
            float2 v3 = upk2(acc[p][3]);
            int rl = tr * 8 + 2 * p;
            if (rl < rem) {
                float4 hv = make_float4(fmaxf(v0.x + bias[0], 0.f),
                                        fmaxf(v1.x + bias[1], 0.f),
                                        fmaxf(v2.x + bias[2], 0.f),
                                        fmaxf(v3.x + bias[3], 0.f));
                ((float4*)(g_h + (size_t)(r0 + rl) * 128))[tc] = hv;
                hs[0] += hv.x; hs[1] += hv.y; hs[2] += hv.z; hs[3] += hv.w;
            }
            if (rl + 1 < rem) {
                float4 hv = make_float4(fmaxf(v0.y + bias[0], 0.f),
                                        fmaxf(v1.y + bias[1], 0.f),
                                        fmaxf(v2.y + bias[2], 0.f),
                                        fmaxf(v3.y + bias[3], 0.f));
                ((float4*)(g_h + (size_t)(r0 + rl + 1) * 128))[tc] = hv;
                hs[0] += hv.x; hs[1] += hv.y; hs[2] += hv.z; hs[3] += hv.w;
            }
        }
    }

    // deterministic reduce of h col-sums over tr, then lam2 = hm @ l2w^T
    __syncthreads();
    ((float4*)s_red[tr])[tc] = make_float4(hs[0], hs[1], hs[2], hs[3]);
    __syncthreads();
    if (tid < 128) {
        float s = 0.f;
#pragma unroll
        for (int i = 0; i < 16; ++i) s += s_red[i][tid];
        float cnt = (float)max(hi - lo, 1);
        s_hm[tid] = s / cnt;
    }
    __syncthreads();
    if (tid < 128) {
        const float* w = l2w + tid * 128;
        float a = 0.f;
#pragma unroll 8
        for (int k = 0; k < 128; ++k) a += s_hm[k] * w[k];
        g_lam2[g * 128 + tid] = a;
    }
}

// ---------------- K4: y0 = h @ g2w^T + g2b - lam2[g]; in-place over g_h; BN partials ----------------
__global__ __launch_bounds__(512, 1) void k_gemm2(
    const float* __restrict__ g2w, const float* __restrict__ g2b, int N) {
    extern __shared__ float sm[];
    float* ws = sm;                 // [128][132]
    float* xs = sm + 128 * 132;     // [128][132]
    __shared__ __align__(16) float s_red[16][128];

    int g   = blockIdx.x;
    int lo  = g_seg[g], hi = g_seg[g + 1];
    int tid = threadIdx.x;
    int tc  = tid & 31, tr = tid >> 5;

    const float4* w4 = (const float4*)g2w;
    for (int idx = tid; idx < 128 * 32; idx += 512) {
        int j = idx >> 5, k4 = idx & 31;
        float4 v = w4[idx];
        int k = 4 * k4;
        ws[(k + 0) * 132 + j] = v.x;
        ws[(k + 1) * 132 + j] = v.y;
        ws[(k + 2) * 132 + j] = v.z;
        ws[(k + 3) * 132 + j] = v.w;
    }

    float bias[4];
#pragma unroll
    for (int c = 0; c < 4; ++c)
        bias[c] = g2b[4 * tc + c] - g_lam2[g * 128 + 4 * tc + c];

    float ssum[4] = {0.f, 0.f, 0.f, 0.f};
    float ssq[4]  = {0.f, 0.f, 0.f, 0.f};

    for (int r0 = lo; r0 < hi; r0 += 128) {
        int rem = min(128, hi - r0);
        __syncthreads();

        const float4* h4 = (const float4*)g_h;
        for (int idx = tid; idx < 128 * 32; idx += 512) {
            int r = idx >> 5, k4 = idx & 31;
            float4 v = make_float4(0.f, 0.f, 0.f, 0.f);
            if (r < rem) v = h4[(size_t)(r0 + r) * 32 + k4];
            int k = 4 * k4;
            xs[(k + 0) * 132 + r] = v.x;
            xs[(k + 1) * 132 + r] = v.y;
            xs[(k + 2) * 132 + r] = v.z;
            xs[(k + 3) * 132 + r] = v.w;
        }
        __syncthreads();

        unsigned long long acc[4][4];
#pragma unroll
        for (int p = 0; p < 4; ++p)
#pragma unroll
            for (int c = 0; c < 4; ++c) acc[p][c] = 0ull;

#pragma unroll 4
        for (int k = 0; k < 128; ++k) {
            const float4* xr = (const float4*)(xs + k * 132);
            float4 xa = xr[2 * tr];
            float4 xb = xr[2 * tr + 1];
            float4 wv = ((const float4*)(ws + k * 132))[tc];
            unsigned long long xp[4] = {pk2(xa.x, xa.y), pk2(xa.z, xa.w),
                                        pk2(xb.x, xb.y), pk2(xb.z, xb.w)};
            unsigned long long wp[4] = {pk2(wv.x, wv.x), pk2(wv.y, wv.y),
                                        pk2(wv.z, wv.z), pk2(wv.w, wv.w)};
#pragma unroll
            for (int p = 0; p < 4; ++p)
#pragma unroll
                for (int c = 0; c < 4; ++c)
                    acc[p][c] = fma2(xp[p], wp[c], acc[p][c]);
        }

#pragma unroll
        for (int p = 0; p < 4; ++p) {
            float2 v0 = upk2(acc[p][0]);
            float2 v1 = upk2(acc[p][1]);
            float2 v2 = upk2(acc[p][2]);
            float2 v3 = upk2(acc[p][3]);
            int rl = tr * 8 + 2 * p;
            if (rl < rem) {
                float4 yv = make_float4(v0.x + bias[0], v1.x + bias[1],
                                        v2.x + bias[2], v3.x + bias[3]);
                ((float4*)(g_h + (size_t)(r0 + rl) * 128))[tc] = yv;
                ssum[0] += yv.x; ssum[1] += yv.y; ssum[2] += yv.z; ssum[3] += yv.w;
                ssq[0] += yv.x * yv.x; ssq[1] += yv.y * yv.y;
                ssq[2] += yv.z * yv.z; ssq[3] += yv.w * yv.w;
            }
            if (rl + 1 < rem) {
                float4 yv = make_float4(v0.y + bias[0], v1.y + bias[1],
                                        v2.y + bias[2], v3.y + bias[3]);
                ((float4*)(g_h + (size_t)(r0 + rl + 1) * 128))[tc] = yv;
                ssum[0] += yv.x; ssum[1] += yv.y; ssum[2] += yv.z; ssum[3] += yv.w;
                ssq[0] += yv.x * yv.x; ssq[1] += yv.y * yv.y;
                ssq[2] += yv.z * yv.z; ssq[3] += yv.w * yv.w;
            }
        }
    }

    // deterministic per-graph BN partials
    __syncthreads();
    ((float4*)s_red[tr])[tc] = make_float4(ssum[0], ssum[1], ssum[2], ssum[3]);
    __syncthreads();
    float a = 0.f;
    if (tid < 128) {
#pragma unroll
        for (int i = 0; i < 16; ++i) a += s_red[i][tid];
    }
    __syncthreads();
    ((float4*)s_red[tr])[tc] = make_float4(ssq[0], ssq[1], ssq[2], ssq[3]);
    __syncthreads();
    if (tid < 128) {
        float b = 0.f;
#pragma unroll
        for (int i = 0; i < 16; ++i) b += s_red[i][tid];
        g_psum[g * 128 + tid] = a;
        g_psq[g * 128 + tid]  = b;
    }
}

// ---------------- K5: BN stats -> scale/shift ----------------
__global__ void k_stats(const float* __restrict__ bn_g, const float* __restrict__ bn_b, int N) {
    int t = threadIdx.x;  // 128
    float s = 0.f, q = 0.f;
    for (int g = 0; g < NG; ++g) {
        s += g_psum[g * 128 + t];
        q += g_psq[g * 128 + t];
    }
    float invN = 1.f / (float)N;
    float mu  = s * invN;
    float var = fmaxf(q * invN - mu * mu, 0.f);
    float sc  = rsqrtf(var + BN_EPS) * bn_g[t];
    g_scale[t] = sc;
    g_shift[t] = bn_b[t] - mu * sc;
}

// ---------------- K6: out = x + y0*scale + shift ----------------
__global__ void k_out(const float* __restrict__ x, float* __restrict__ out, int total4) {
    int i = blockIdx.x * blockDim.x + threadIdx.x;
    if (i >= total4) return;
    int j4 = i & 31;
    float4 sc = ((const float4*)g_scale)[j4];
    float4 sh = ((const float4*)g_shift)[j4];
    float4 xv = ((const float4*)x)[i];
    float4 yv = ((const float4*)g_h)[i];
    float4 o;
    o.x = xv.x + yv.x * sc.x + sh.x;
    o.y = xv.y + yv.y * sc.y + sh.y;
    o.z = xv.z + yv.z * sc.z + sh.z;
    o.w = xv.w + yv.w * sc.w + sh.w;
    ((float4*)out)[i] = o;
}

// ---------------- launch ----------------
extern "C" void kernel_launch(void* const* d_in, const int* in_sizes, int n_in,
                              void* d_out, int out_size) {
    const float* x     = (const float*)d_in[0];
    const int*   batch = (const int*)d_in[1];
    const float* pers0 = (const float*)d_in[2];
    const float* g1w   = (const float*)d_in[3];
    const float* g1b   = (const float*)d_in[4];
    const float* l1w   = (const float*)d_in[5];
    const float* g2w   = (const float*)d_in[6];
    const float* g2b   = (const float*)d_in[7];
    const float* l2w   = (const float*)d_in[8];
    const float* bng   = (const float*)d_in[9];
    const float* bnb   = (const float*)d_in[10];
    float* out = (float*)d_out;
    int N = in_sizes[0] / 128;

    const int smem1 = 2 * 144 * 132 * 4;  // 152064 B
    const int smem2 = 2 * 128 * 132 * 4;  // 135168 B
    cudaFuncSetAttribute(k_gemm1, cudaFuncAttributeMaxDynamicSharedMemorySize, smem1);
    cudaFuncSetAttribute(k_gemm2, cudaFuncAttributeMaxDynamicSharedMemorySize, smem2);

    k_bounds<<<(NG + 256) / 256, 256>>>(batch, N);
    k_lam1<<<NG, 288>>>(x, pers0, l1w, N);
    k_gemm1<<<NG, 512, smem1>>>(x, pers0, g1w, g1b, l2w, N);
    k_gemm2<<<NG, 512, smem2>>>(g2w, g2b, N);
    k_stats<<<1, 128>>>(bng, bnb, N);
    int total4 = N * 32;
    k_out<<<(total4 + 255) / 256, 256>>>(x, out, total4);
}

// round 5
// speedup vs baseline: 1.1903x; 1.1903x over previous
#include <cuda_runtime.h>
#include <cstdint>

#define NG   2048
#define MAXN 500000
#define BN_EPS 1e-5f

// ---------------- scratch (device globals; no allocation allowed) ----------------
__device__ __align__(16) float g_h[(size_t)MAXN * 128];   // h, then y0 in-place
__device__ __align__(16) float g_lam1[NG * 128];
__device__ __align__(16) float g_lam2[NG * 128];
__device__ __align__(16) float g_psum[NG * 128];
__device__ __align__(16) float g_psq[NG * 128];
__device__ __align__(16) float g_scale[128];
__device__ __align__(16) float g_shift[128];
__device__ int g_seg[NG + 1];

typedef unsigned long long ull;

// ---------------- packed f32x2 helpers ----------------
__device__ __forceinline__ ull pk2(float a, float b) {
    ull r;
    asm("mov.b64 %0, {%1, %2};" : "=l"(r) : "f"(a), "f"(b));
    return r;
}
__device__ __forceinline__ ull fma2(ull a, ull b, ull c) {
    ull d;
    asm("fma.rn.f32x2 %0, %1, %2, %3;" : "=l"(d) : "l"(a), "l"(b), "l"(c));
    return d;
}
__device__ __forceinline__ float2 upk2(ull v) {
    float2 f;
    asm("mov.b64 {%0, %1}, %2;" : "=f"(f.x), "=f"(f.y) : "l"(v));
    return f;
}

// ---------------- cp.async helpers ----------------
__device__ __forceinline__ uint32_t smaddr(const void* p) {
    return (uint32_t)__cvta_generic_to_shared(p);
}
__device__ __forceinline__ void cp16(uint32_t d, const void* s, int n) {
    asm volatile("cp.async.ca.shared.global [%0], [%1], 16, %2;\n" :: "r"(d), "l"(s), "r"(n));
}
__device__ __forceinline__ void cp4(uint32_t d, const void* s, int n) {
    asm volatile("cp.async.ca.shared.global [%0], [%1], 4, %2;\n" :: "r"(d), "l"(s), "r"(n));
}
#define CP_COMMIT() asm volatile("cp.async.commit_group;\n" ::: "memory")
#define CP_WAIT0()  asm volatile("cp.async.wait_group 0;\n" ::: "memory")

// ---------------- K0: segment bounds via binary search (batch sorted) ----------------
__global__ void k_bounds(const int* __restrict__ batch, int N) {
    int g = blockIdx.x * blockDim.x + threadIdx.x;
    if (g > NG) return;
    int lo = 0, hi = N;
    while (lo < hi) {
        int mid = (lo + hi) >> 1;
        if (batch[mid] < g) lo = mid + 1; else hi = mid;
    }
    g_seg[g] = lo;
}

// ---------------- K1: per-graph col-sums of x0 (144 cols) + lam1 = xm @ l1w^T ----------------
__global__ void k_lam1(const float* __restrict__ x, const float* __restrict__ pers0,
                       const float* __restrict__ l1w, int N) {
    __shared__ float s_sum[2][144];
    __shared__ float s_xm[144];
    int g  = blockIdx.x;
    int lo = g_seg[g], hi = g_seg[g + 1];
    int t  = threadIdx.x;
    int phase = t / 144, col = t - phase * 144;

    float acc = 0.f;
    if (col < 128) {
        const float* p = x + col;
        for (int r = lo + phase; r < hi; r += 2) acc += p[(size_t)r * 128];
    } else {
        int j = col - 128;
        int pp = j >> 1, c = j & 1;
        const float* p = pers0 + (size_t)pp * 2 * N + c;
        for (int r = lo + phase; r < hi; r += 2) acc += p[2 * (size_t)r];
    }
    s_sum[phase][col] = acc;
    __syncthreads();
    if (t < 144) {
        float cnt = (float)max(hi - lo, 1);
        s_xm[t] = (s_sum[0][t] + s_sum[1][t]) / cnt;
    }
    __syncthreads();
    if (t < 128) {
        const float* w = l1w + t * 144;
        float a = 0.f;
#pragma unroll 8
        for (int k = 0; k < 144; ++k) a += s_xm[k] * w[k];
        g_lam1[g * 128 + t] = a;
    }
}

// ---------------- K2: h = relu(x0 @ g1w^T + g1b - lam1[g]) + h col-sums + lam2 ----------------
// One block per graph, 512 threads. cp.async double-stage: gmem -> land (row-major),
// conflict-free smem transpose land -> xs (k-major), f32x2 compute.
// NO static smem: reduction buffers alias `land` (dead after main loop).
__global__ __launch_bounds__(512, 1) void k_gemm1(
    const float* __restrict__ x, const float* __restrict__ pers0,
    const float* __restrict__ g1w, const float* __restrict__ g1b,
    const float* __restrict__ l2w, int N) {
    extern __shared__ float sm[];
    float* ws   = sm;                         // [144][132] transposed weights
    float* xs   = sm + 144 * 132;             // [144][132] k-major x0 tile
    float* land = sm + 2 * 144 * 132;         // [128][148] row-major landing
    const int SL = 148;

    int g   = blockIdx.x;
    int lo  = g_seg[g], hi = g_seg[g + 1];
    int tid = threadIdx.x;
    int tc  = tid & 31, tr = tid >> 5;   // cols 4*tc.., row-pairs from 8*tr..

    // ---- issue cp.async loads for one 128-row tile into land ----
    auto issue = [&](int r0, int rem) {
#pragma unroll
        for (int it = 0; it < 8; ++it) {
            int idx = tid + it * 512;
            int r = idx >> 5, k4 = idx & 31;
            int rg = r0 + min(r, rem - 1);
            int n  = (r < rem) ? 16 : 0;
            cp16(smaddr(land + r * SL + 4 * k4), x + (size_t)rg * 128 + 4 * k4, n);
        }
#pragma unroll
        for (int it = 0; it < 4; ++it) {
            int idx = tid + it * 512;
            int r = idx >> 4, q = idx & 15;
            int pp = q >> 1, c = q & 1;
            int rg = r0 + min(r, rem - 1);
            int n  = (r < rem) ? 4 : 0;
            cp4(smaddr(land + r * SL + 128 + q),
                pers0 + (size_t)pp * 2 * N + 2 * (size_t)rg + c, n);
        }
    };

    if (lo < hi) { issue(lo, min(128, hi - lo)); CP_COMMIT(); }

    // ---- stage ws transposed, conflict-free lane map (lanes: 16 j x 2 k4) ----
    {
        const float4* w4 = (const float4*)g1w;
        for (int it = 0; it < 9; ++it) {
            int idx = tid + it * 512;            // [0, 128*36)
            int b = idx & 15, a = (idx >> 4) & 1, c = idx >> 5;  // c in [0,144)
            int j  = (c & 7) * 16 + b;
            int k4 = (c >> 3) * 2 + a;           // [0,36)
            float4 v = w4[j * 36 + k4];
            int k = 4 * k4;
            ws[(k + 0) * 132 + j] = v.x;
            ws[(k + 1) * 132 + j] = v.y;
            ws[(k + 2) * 132 + j] = v.z;
            ws[(k + 3) * 132 + j] = v.w;
        }
    }

    float bias[4];
#pragma unroll
    for (int c = 0; c < 4; ++c)
        bias[c] = g1b[4 * tc + c] - g_lam1[g * 128 + 4 * tc + c];

    float hs[4] = {0.f, 0.f, 0.f, 0.f};

    for (int r0 = lo; r0 < hi; r0 += 128) {
        int rem = min(128, hi - r0);
        CP_WAIT0();
        __syncthreads();   // land ready for all; previous compute done (xs reusable)

        // ---- transpose land -> xs (conflict-free lane map) ----
#pragma unroll
        for (int it = 0; it < 9; ++it) {
            int idx = tid + it * 512;            // [0, 128*36)
            int b = idx & 15, a = (idx >> 4) & 1, c = idx >> 5;
            int r  = (c & 7) * 16 + b;
            int k4 = (c >> 3) * 2 + a;
            float4 v = *(const float4*)(land + r * SL + 4 * k4);
            int k = 4 * k4;
            xs[(k + 0) * 132 + r] = v.x;
            xs[(k + 1) * 132 + r] = v.y;
            xs[(k + 2) * 132 + r] = v.z;
            xs[(k + 3) * 132 + r] = v.w;
        }
        __syncthreads();

        // prefetch next tile while computing
        int nr0 = r0 + 128;
        if (nr0 < hi) { issue(nr0, min(128, hi - nr0)); CP_COMMIT(); }

        ull acc[4][4];
#pragma unroll
        for (int p = 0; p < 4; ++p)
#pragma unroll
            for (int c = 0; c < 4; ++c) acc[p][c] = 0ull;

#pragma unroll 4
        for (int k = 0; k < 144; ++k) {
            const float* xk = xs + k * 132 + 8 * tr;
            ulonglong2 xa = *(const ulonglong2*)(xk);      // row pairs (0,1),(2,3)
            ulonglong2 xb = *(const ulonglong2*)(xk + 4);  // row pairs (4,5),(6,7)
            float4 wv = *(const float4*)(ws + k * 132 + 4 * tc);
            ull wp0 = pk2(wv.x, wv.x), wp1 = pk2(wv.y, wv.y);
            ull wp2 = pk2(wv.z, wv.z), wp3 = pk2(wv.w, wv.w);
            acc[0][0] = fma2(xa.x, wp0, acc[0][0]);
            acc[0][1] = fma2(xa.x, wp1, acc[0][1]);
            acc[0][2] = fma2(xa.x, wp2, acc[0][2]);
            acc[0][3] = fma2(xa.x, wp3, acc[0][3]);
            acc[1][0] = fma2(xa.y, wp0, acc[1][0]);
            acc[1][1] = fma2(xa.y, wp1, acc[1][1]);
            acc[1][2] = fma2(xa.y, wp2, acc[1][2]);
            acc[1][3] = fma2(xa.y, wp3, acc[1][3]);
            acc[2][0] = fma2(xb.x, wp0, acc[2][0]);
            acc[2][1] = fma2(xb.x, wp1, acc[2][1]);
            acc[2][2] = fma2(xb.x, wp2, acc[2][2]);
            acc[2][3] = fma2(xb.x, wp3, acc[2][3]);
            acc[3][0] = fma2(xb.y, wp0, acc[3][0]);
            acc[3][1] = fma2(xb.y, wp1, acc[3][1]);
            acc[3][2] = fma2(xb.y, wp2, acc[3][2]);
            acc[3][3] = fma2(xb.y, wp3, acc[3][3]);
        }

        // epilogue: relu, store h, accumulate col sums (valid rows only)
#pragma unroll
        for (int p = 0; p < 4; ++p) {
            float2 v0 = upk2(acc[p][0]);
            float2 v1 = upk2(acc[p][1]);
            float2 v2 = upk2(acc[p][2]);
            float2 v3 = upk2(acc[p][3]);
            int rl = tr * 8 + 2 * p;
            if (rl < rem) {
                float4 hv = make_float4(fmaxf(v0.x + bias[0], 0.f),
                                        fmaxf(v1.x + bias[1], 0.f),
                                        fmaxf(v2.x + bias[2], 0.f),
                                        fmaxf(v3.x + bias[3], 0.f));
                ((float4*)(g_h + (size_t)(r0 + rl) * 128))[tc] = hv;
                hs[0] += hv.x; hs[1] += hv.y; hs[2] += hv.z; hs[3] += hv.w;
            }
            if (rl + 1 < rem) {
                float4 hv = make_float4(fmaxf(v0.y + bias[0], 0.f),
                                        fmaxf(v1.y + bias[1], 0.f),
                                        fmaxf(v2.y + bias[2], 0.f),
                                        fmaxf(v3.y + bias[3], 0.f));
                ((float4*)(g_h + (size_t)(r0 + rl + 1) * 128))[tc] = hv;
                hs[0] += hv.x; hs[1] += hv.y; hs[2] += hv.z; hs[3] += hv.w;
            }
        }
    }

    // deterministic reduce of h col-sums, then lam2 = hm @ l2w^T
    // reduction buffers alias `land` (dead now; sync orders reuse)
    float* s_red = land;            // [16][128]
    float* s_hm  = land + 16 * 128; // [128]
    __syncthreads();
    ((float4*)(s_red + tr * 128))[tc] = make_float4(hs[0], hs[1], hs[2], hs[3]);
    __syncthreads();
    if (tid < 128) {
        float s = 0.f;
#pragma unroll
        for (int i = 0; i < 16; ++i) s += s_red[i * 128 + tid];
        float cnt = (float)max(hi - lo, 1);
        s_hm[tid] = s / cnt;
    }
    __syncthreads();
    if (tid < 128) {
        const float* w = l2w + tid * 128;
        float a = 0.f;
#pragma unroll 8
        for (int k = 0; k < 128; ++k) a += s_hm[k] * w[k];
        g_lam2[g * 128 + tid] = a;
    }
}

// ---------------- K4: y0 = h @ g2w^T + g2b - lam2[g]; in-place; BN partials ----------------
__global__ __launch_bounds__(512, 1) void k_gemm2(
    const float* __restrict__ g2w, const float* __restrict__ g2b, int N) {
    extern __shared__ float sm[];
    float* ws   = sm;                         // [128][132]
    float* xs   = sm + 128 * 132;             // [128][132]
    float* land = sm + 2 * 128 * 132;         // [128][132] row-major landing
    const int SL = 132;

    int g   = blockIdx.x;
    int lo  = g_seg[g], hi = g_seg[g + 1];
    int tid = threadIdx.x;
    int tc  = tid & 31, tr = tid >> 5;

    auto issue = [&](int r0, int rem) {
#pragma unroll
        for (int it = 0; it < 8; ++it) {
            int idx = tid + it * 512;
            int r = idx >> 5, k4 = idx & 31;
            int rg = r0 + min(r, rem - 1);
            int n  = (r < rem) ? 16 : 0;
            cp16(smaddr(land + r * SL + 4 * k4), g_h + (size_t)rg * 128 + 4 * k4, n);
        }
    };

    if (lo < hi) { issue(lo, min(128, hi - lo)); CP_COMMIT(); }

    {
        const float4* w4 = (const float4*)g2w;
        for (int it = 0; it < 8; ++it) {
            int idx = tid + it * 512;            // [0, 128*32)
            int b = idx & 15, a = (idx >> 4) & 1, c = idx >> 5;  // c in [0,128)
            int j  = (c & 7) * 16 + b;
            int k4 = (c >> 3) * 2 + a;           // [0,32)
            float4 v = w4[j * 32 + k4];
            int k = 4 * k4;
            ws[(k + 0) * 132 + j] = v.x;
            ws[(k + 1) * 132 + j] = v.y;
            ws[(k + 2) * 132 + j] = v.z;
            ws[(k + 3) * 132 + j] = v.w;
        }
    }

    float bias[4];
#pragma unroll
    for (int c = 0; c < 4; ++c)
        bias[c] = g2b[4 * tc + c] - g_lam2[g * 128 + 4 * tc + c];

    float ssum[4] = {0.f, 0.f, 0.f, 0.f};
    float ssq[4]  = {0.f, 0.f, 0.f, 0.f};

    for (int r0 = lo; r0 < hi; r0 += 128) {
        int rem = min(128, hi - r0);
        CP_WAIT0();
        __syncthreads();

#pragma unroll
        for (int it = 0; it < 8; ++it) {
            int idx = tid + it * 512;
            int b = idx & 15, a = (idx >> 4) & 1, c = idx >> 5;
            int r  = (c & 7) * 16 + b;
            int k4 = (c >> 3) * 2 + a;
            float4 v = *(const float4*)(land + r * SL + 4 * k4);
            int k = 4 * k4;
            xs[(k + 0) * 132 + r] = v.x;
            xs[(k + 1) * 132 + r] = v.y;
            xs[(k + 2) * 132 + r] = v.z;
            xs[(k + 3) * 132 + r] = v.w;
        }
        __syncthreads();

        int nr0 = r0 + 128;
        if (nr0 < hi) { issue(nr0, min(128, hi - nr0)); CP_COMMIT(); }

        ull acc[4][4];
#pragma unroll
        for (int p = 0; p < 4; ++p)
#pragma unroll
            for (int c = 0; c < 4; ++c) acc[p][c] = 0ull;

#pragma unroll 4
        for (int k = 0; k < 128; ++k) {
            const float* xk = xs + k * 132 + 8 * tr;
            ulonglong2 xa = *(const ulonglong2*)(xk);
            ulonglong2 xb = *(const ulonglong2*)(xk + 4);
            float4 wv = *(const float4*)(ws + k * 132 + 4 * tc);
            ull wp0 = pk2(wv.x, wv.x), wp1 = pk2(wv.y, wv.y);
            ull wp2 = pk2(wv.z, wv.z), wp3 = pk2(wv.w, wv.w);
            acc[0][0] = fma2(xa.x, wp0, acc[0][0]);
            acc[0][1] = fma2(xa.x, wp1, acc[0][1]);
            acc[0][2] = fma2(xa.x, wp2, acc[0][2]);
            acc[0][3] = fma2(xa.x, wp3, acc[0][3]);
            acc[1][0] = fma2(xa.y, wp0, acc[1][0]);
            acc[1][1] = fma2(xa.y, wp1, acc[1][1]);
            acc[1][2] = fma2(xa.y, wp2, acc[1][2]);
            acc[1][3] = fma2(xa.y, wp3, acc[1][3]);
            acc[2][0] = fma2(xb.x, wp0, acc[2][0]);
            acc[2][1] = fma2(xb.x, wp1, acc[2][1]);
            acc[2][2] = fma2(xb.x, wp2, acc[2][2]);
            acc[2][3] = fma2(xb.x, wp3, acc[2][3]);
            acc[3][0] = fma2(xb.y, wp0, acc[3][0]);
            acc[3][1] = fma2(xb.y, wp1, acc[3][1]);
            acc[3][2] = fma2(xb.y, wp2, acc[3][2]);
            acc[3][3] = fma2(xb.y, wp3, acc[3][3]);
        }

#pragma unroll
        for (int p = 0; p < 4; ++p) {
            float2 v0 = upk2(acc[p][0]);
            float2 v1 = upk2(acc[p][1]);
            float2 v2 = upk2(acc[p][2]);
            float2 v3 = upk2(acc[p][3]);
            int rl = tr * 8 + 2 * p;
            if (rl < rem) {
                float4 yv = make_float4(v0.x + bias[0], v1.x + bias[1],
                                        v2.x + bias[2], v3.x + bias[3]);
                ((float4*)(g_h + (size_t)(r0 + rl) * 128))[tc] = yv;
                ssum[0] += yv.x; ssum[1] += yv.y; ssum[2] += yv.z; ssum[3] += yv.w;
                ssq[0] += yv.x * yv.x; ssq[1] += yv.y * yv.y;
                ssq[2] += yv.z * yv.z; ssq[3] += yv.w * yv.w;
            }
            if (rl + 1 < rem) {
                float4 yv = make_float4(v0.y + bias[0], v1.y + bias[1],
                                        v2.y + bias[2], v3.y + bias[3]);
                ((float4*)(g_h + (size_t)(r0 + rl + 1) * 128))[tc] = yv;
                ssum[0] += yv.x; ssum[1] += yv.y; ssum[2] += yv.z; ssum[3] += yv.w;
                ssq[0] += yv.x * yv.x; ssq[1] += yv.y * yv.y;
                ssq[2] += yv.z * yv.z; ssq[3] += yv.w * yv.w;
            }
        }
    }

    // deterministic per-graph BN partials; reduction buffer aliases `land`
    float* s_red = land;  // [16][128]
    __syncthreads();
    ((float4*)(s_red + tr * 128))[tc] = make_float4(ssum[0], ssum[1], ssum[2], ssum[3]);
    __syncthreads();
    float a = 0.f;
    if (tid < 128) {
#pragma unroll
        for (int i = 0; i < 16; ++i) a += s_red[i * 128 + tid];
    }
    __syncthreads();
    ((float4*)(s_red + tr * 128))[tc] = make_float4(ssq[0], ssq[1], ssq[2], ssq[3]);
    __syncthreads();
    if (tid < 128) {
        float b = 0.f;
#pragma unroll
        for (int i = 0; i < 16; ++i) b += s_red[i * 128 + tid];
        g_psum[g * 128 + tid] = a;
        g_psq[g * 128 + tid]  = b;
    }
}

// ---------------- K5: BN stats -> scale/shift ----------------
__global__ void k_stats(const float* __restrict__ bn_g, const float* __restrict__ bn_b, int N) {
    int t = threadIdx.x;  // 128
    float s = 0.f, q = 0.f;
    for (int g = 0; g < NG; ++g) {
        s += g_psum[g * 128 + t];
        q += g_psq[g * 128 + t];
    }
    float invN = 1.f / (float)N;
    float mu  = s * invN;
    float var = fmaxf(q * invN - mu * mu, 0.f);
    float sc  = rsqrtf(var + BN_EPS) * bn_g[t];
    g_scale[t] = sc;
    g_shift[t] = bn_b[t] - mu * sc;
}

// ---------------- K6: out = x + y0*scale + shift ----------------
__global__ void k_out(const float* __restrict__ x, float* __restrict__ out, int total4) {
    int i = blockIdx.x * blockDim.x + threadIdx.x;
    if (i >= total4) return;
    int j4 = i & 31;
    float4 sc = ((const float4*)g_scale)[j4];
    float4 sh = ((const float4*)g_shift)[j4];
    float4 xv = ((const float4*)x)[i];
    float4 yv = ((const float4*)g_h)[i];
    float4 o;
    o.x = xv.x + yv.x * sc.x + sh.x;
    o.y = xv.y + yv.y * sc.y + sh.y;
    o.z = xv.z + yv.z * sc.z + sh.z;
    o.w = xv.w + yv.w * sc.w + sh.w;
    ((float4*)out)[i] = o;
}

// ---------------- launch ----------------
extern "C" void kernel_launch(void* const* d_in, const int* in_sizes, int n_in,
                              void* d_out, int out_size) {
    const float* x     = (const float*)d_in[0];
    const int*   batch = (const int*)d_in[1];
    const float* pers0 = (const float*)d_in[2];
    const float* g1w   = (const float*)d_in[3];
    const float* g1b   = (const float*)d_in[4];
    const float* l1w   = (const float*)d_in[5];
    const float* g2w   = (const float*)d_in[6];
    const float* g2b   = (const float*)d_in[7];
    const float* l2w   = (const float*)d_in[8];
    const float* bng   = (const float*)d_in[9];
    const float* bnb   = (const float*)d_in[10];
    float* out = (float*)d_out;
    int N = in_sizes[0] / 128;

    const int smem1 = (2 * 144 * 132 + 128 * 148) * 4;  // 227,840 B (no static smem)
    const int smem2 = (3 * 128 * 132) * 4;              // 202,752 B (no static smem)
    cudaFuncSetAttribute(k_gemm1, cudaFuncAttributeMaxDynamicSharedMemorySize, smem1);
    cudaFuncSetAttribute(k_gemm2, cudaFuncAttributeMaxDynamicSharedMemorySize, smem2);

    k_bounds<<<(NG + 256) / 256, 256>>>(batch, N);
    k_lam1<<<NG, 288>>>(x, pers0, l1w, N);
    k_gemm1<<<NG, 512, smem1>>>(x, pers0, g1w, g1b, l2w, N);
    k_gemm2<<<NG, 512, smem2>>>(g2w, g2b, N);
    k_stats<<<1, 128>>>(bng, bnb, N);
    int total4 = N * 32;
    k_out<<<(total4 + 255) / 256, 256>>>(x, out, total4);
}